// round 2
// baseline (speedup 1.0000x reference)
#include <cuda_runtime.h>
#include <cuda_bf16.h>

#define NN   2048
#define EE   65536
#define FIN  128
#define HH   16
#define N2   (NN * NN)

// ---------------- scratch (no allocations allowed) ----------------
// deg/acc arrays are accumulated via atomics each call; they are reset to zero
// at the END of each call (tail of k_pair) so the next graph replay starts
// clean. Load-time zero-init covers the very first call.
__device__ __align__(16) float g_deg[NN];
__device__ __align__(16) float g_xw1[NN * HH];
__device__ __align__(16) float g_acc1[NN * HH];
__device__ __align__(16) float g_hw2[NN * 2];
__device__ __align__(16) float g_acc2[NN * 2];
__device__ __align__(16) float g_A[NN * HH];   // h @ Wc1[0:16] + bc1
__device__ __align__(16) float g_B[NN * HH];   // h @ Wc1[16:32]

// ---------------- per-thread edge_index layout detection ----------------
// Read the first 8 u64 words (64B, within bounds for either dtype).
// int64 data: all values < 2048, so OR < 2048.
// int32 data: each u64 packs two node ids; OR's high half is nonzero unless
// all 8 odd-position ids are 0 (prob (1/2048)^8 ~ 6e-27).
__device__ __forceinline__ bool detect_is32(const void* ei) {
    const unsigned long long* p = (const unsigned long long*)ei;
    unsigned long long v = p[0] | p[1] | p[2] | p[3] | p[4] | p[5] | p[6] | p[7];
    return v >= 2048ULL;
}

__device__ __forceinline__ void ld_edge(const void* ei, int e, bool is32,
                                        int& s, int& d) {
    if (is32) {
        s = ((const int*)ei)[e];
        d = ((const int*)ei)[EE + e];
    } else {
        s = (int)(((const long long*)ei)[e]);
        d = (int)(((const long long*)ei)[EE + e]);
    }
}

__device__ __forceinline__ void red_add_v4(float* p, float a, float b, float c, float d) {
    asm volatile("red.global.add.v4.f32 [%0], {%1,%2,%3,%4};"
                 :: "l"(p), "f"(a), "f"(b), "f"(c), "f"(d) : "memory");
}
__device__ __forceinline__ void red_add_v2(float* p, float a, float b) {
    asm volatile("red.global.add.v2.f32 [%0], {%1,%2};"
                 :: "l"(p), "f"(a), "f"(b) : "memory");
}

// ================= K1: xw1 = x@W1, degree accumulation, self-loops ========
__global__ void k1_xw1_deg(const float* __restrict__ x,
                           const float* __restrict__ W1,
                           const void* __restrict__ ei) {
    int id = blockIdx.x * blockDim.x + threadIdx.x;   // 65536 threads
    if (id < NN) atomicAdd(&g_deg[id], 1.f);          // self loop
    if (id < EE) {
        bool is32 = detect_is32(ei);
        int s, d;
        ld_edge(ei, id, is32, s, d);
        atomicAdd(&g_deg[d], 1.f);
    }
    if (id < NN * HH) {
        int i = id >> 4, f = id & 15;
        const float* xr = x + i * FIN;
        float sum = 0.f;
        #pragma unroll 8
        for (int k = 0; k < FIN; k++) sum = fmaf(xr[k], W1[k * HH + f], sum);
        g_xw1[id] = sum;
    }
}

// ================= K2: scatter layer 1 ====================================
__global__ void k2_scatter1(const void* __restrict__ ei) {
    int e = blockIdx.x * blockDim.x + threadIdx.x;
    if (e >= EE) return;
    bool is32 = detect_is32(ei);
    int s, d;
    ld_edge(ei, e, is32, s, d);
    float nrm = rsqrtf(g_deg[s]) * rsqrtf(g_deg[d]);
    const float4* xs = (const float4*)&g_xw1[s * HH];
    float4 v0 = xs[0], v1 = xs[1], v2 = xs[2], v3 = xs[3];
    float* ad = &g_acc1[d * HH];
    red_add_v4(ad + 0,  nrm * v0.x, nrm * v0.y, nrm * v0.z, nrm * v0.w);
    red_add_v4(ad + 4,  nrm * v1.x, nrm * v1.y, nrm * v1.z, nrm * v1.w);
    red_add_v4(ad + 8,  nrm * v2.x, nrm * v2.y, nrm * v2.z, nrm * v2.w);
    red_add_v4(ad + 12, nrm * v3.x, nrm * v3.y, nrm * v3.z, nrm * v3.w);
}

// ================= K3: h = relu(gcn1); hw2 = h@W2; A/B for pair MLP =======
__global__ void k3_hAB(const float* __restrict__ b1, const float* __restrict__ W2,
                       const float* __restrict__ Wc1, const float* __restrict__ bc1) {
    int i = blockIdx.x * blockDim.x + threadIdx.x;
    if (i >= NN) return;
    float d2 = 1.f / g_deg[i];          // dinv^2 for self-loop term
    float h[HH];
    #pragma unroll
    for (int f = 0; f < HH; f++) {
        float v = g_acc1[i * HH + f] + d2 * g_xw1[i * HH + f] + b1[f];
        h[f] = fmaxf(v, 0.f);
    }
    float c0 = 0.f, c1 = 0.f;
    #pragma unroll
    for (int f = 0; f < HH; f++) {
        c0 = fmaf(h[f], W2[f * 2 + 0], c0);
        c1 = fmaf(h[f], W2[f * 2 + 1], c1);
    }
    g_hw2[i * 2 + 0] = c0;
    g_hw2[i * 2 + 1] = c1;
    #pragma unroll
    for (int o = 0; o < HH; o++) {
        float a = bc1[o], b = 0.f;
        #pragma unroll
        for (int f = 0; f < HH; f++) {
            a = fmaf(h[f], Wc1[f * HH + o], a);
            b = fmaf(h[f], Wc1[(HH + f) * HH + o], b);
        }
        g_A[i * HH + o] = a;
        g_B[i * HH + o] = b;
    }
}

// ================= K4: scatter layer 2 ====================================
__global__ void k4_scatter2(const void* __restrict__ ei) {
    int e = blockIdx.x * blockDim.x + threadIdx.x;
    if (e >= EE) return;
    bool is32 = detect_is32(ei);
    int s, d;
    ld_edge(ei, e, is32, s, d);
    float nrm = rsqrtf(g_deg[s]) * rsqrtf(g_deg[d]);
    red_add_v2(&g_acc2[d * 2], nrm * g_hw2[s * 2 + 0], nrm * g_hw2[s * 2 + 1]);
}

// ================= K5: pair MLP + node_out + state reset ==================
// e(i,j) = sigmoid( sum_f relu(A[i][f] + B[j][f]) * Wc2[f] + bc2 )
// block i handles row i (2048 j), 4 j per thread with float4 stores.
__global__ void __launch_bounds__(256) k5_pair(const float* __restrict__ Wc2,
                                               const float* __restrict__ bc2p,
                                               const float* __restrict__ b2,
                                               float* __restrict__ out) {
    int i = blockIdx.x;
    int t = threadIdx.x;

    float a[HH], w[HH];
    {
        const float4* ap = (const float4*)&g_A[i * HH];
        float4 a0 = ap[0], a1 = ap[1], a2 = ap[2], a3 = ap[3];
        a[0]=a0.x; a[1]=a0.y; a[2]=a0.z; a[3]=a0.w;
        a[4]=a1.x; a[5]=a1.y; a[6]=a1.z; a[7]=a1.w;
        a[8]=a2.x; a[9]=a2.y; a[10]=a2.z; a[11]=a2.w;
        a[12]=a3.x; a[13]=a3.y; a[14]=a3.z; a[15]=a3.w;
    }
    #pragma unroll
    for (int f = 0; f < HH; f++) w[f] = Wc2[f];
    float bb = bc2p[0];

    float* eo = out + NN * 2 + (long long)i * NN;
    float* s0 = out + NN * 2 + (long long)N2 + (long long)i * NN;
    float* s1 = out + NN * 2 + 2LL * N2 + (long long)i * NN;
    float fi = (float)i;

    #pragma unroll
    for (int it = 0; it < NN / (256 * 4); it++) {
        int j = (it * 256 + t) * 4;
        float4 sg;
        float* sp = &sg.x;
        #pragma unroll
        for (int q = 0; q < 4; q++) {
            const float4* bp = (const float4*)&g_B[(j + q) * HH];
            float4 b0 = bp[0], b1 = bp[1], b2v = bp[2], b3 = bp[3];
            float s = bb;
            s = fmaf(fmaxf(a[0]  + b0.x, 0.f), w[0],  s);
            s = fmaf(fmaxf(a[1]  + b0.y, 0.f), w[1],  s);
            s = fmaf(fmaxf(a[2]  + b0.z, 0.f), w[2],  s);
            s = fmaf(fmaxf(a[3]  + b0.w, 0.f), w[3],  s);
            s = fmaf(fmaxf(a[4]  + b1.x, 0.f), w[4],  s);
            s = fmaf(fmaxf(a[5]  + b1.y, 0.f), w[5],  s);
            s = fmaf(fmaxf(a[6]  + b1.z, 0.f), w[6],  s);
            s = fmaf(fmaxf(a[7]  + b1.w, 0.f), w[7],  s);
            s = fmaf(fmaxf(a[8]  + b2v.x, 0.f), w[8],  s);
            s = fmaf(fmaxf(a[9]  + b2v.y, 0.f), w[9],  s);
            s = fmaf(fmaxf(a[10] + b2v.z, 0.f), w[10], s);
            s = fmaf(fmaxf(a[11] + b2v.w, 0.f), w[11], s);
            s = fmaf(fmaxf(a[12] + b3.x, 0.f), w[12], s);
            s = fmaf(fmaxf(a[13] + b3.y, 0.f), w[13], s);
            s = fmaf(fmaxf(a[14] + b3.z, 0.f), w[14], s);
            s = fmaf(fmaxf(a[15] + b3.w, 0.f), w[15], s);
            sp[q] = 1.f / (1.f + __expf(-s));
        }
        ((float4*)eo)[it * 256 + t] = sg;
        float4 c0 = make_float4(fi, fi, fi, fi);
        float4 c1 = make_float4((float)j, (float)(j+1), (float)(j+2), (float)(j+3));
        ((float4*)s0)[it * 256 + t] = c0;
        ((float4*)s1)[it * 256 + t] = c1;
    }

    // node_out for node i (thread 0), then reset accumulators for next replay
    if (t == 0) {
        float d2 = 1.f / g_deg[i];
        out[i * 2 + 0] = g_acc2[i * 2 + 0] + d2 * g_hw2[i * 2 + 0] + b2[0];
        out[i * 2 + 1] = g_acc2[i * 2 + 1] + d2 * g_hw2[i * 2 + 1] + b2[1];
    }
    __syncthreads();
    if (t < HH)  g_acc1[i * HH + t] = 0.f;
    if (t == 16) g_acc2[i * 2 + 0] = 0.f;
    if (t == 17) g_acc2[i * 2 + 1] = 0.f;
    if (t == 18) g_deg[i] = 0.f;
}

// ---------------- launch ----------------
extern "C" void kernel_launch(void* const* d_in, const int* in_sizes, int n_in,
                              void* d_out, int out_size) {
    const float* x   = (const float*)d_in[0];
    const void*  ei  = d_in[1];                 // int32 or int64, detected per-thread
    const float* W1  = (const float*)d_in[2];
    const float* b1  = (const float*)d_in[3];
    const float* W2  = (const float*)d_in[4];
    const float* b2  = (const float*)d_in[5];
    const float* Wc1 = (const float*)d_in[6];
    const float* bc1 = (const float*)d_in[7];
    const float* Wc2 = (const float*)d_in[8];
    const float* bc2 = (const float*)d_in[9];
    float* out = (float*)d_out;

    k1_xw1_deg<<<EE / 256, 256>>>(x, W1, ei);
    k2_scatter1<<<EE / 256, 256>>>(ei);
    k3_hAB<<<NN / 256, 256>>>(b1, W2, Wc1, bc1);
    k4_scatter2<<<EE / 256, 256>>>(ei);
    k5_pair<<<NN, 256>>>(Wc2, bc2, b2, out);
}